// round 6
// baseline (speedup 1.0000x reference)
#include <cuda_runtime.h>
#include <math.h>

#define NB 256
#define NC 1000
#define ND 128
#define NQ 262144
#define RPB 4

// d_out flat layout (in-order tuple concat):
//   output   [256,1000]  @ 0
//   output2  [256,1000]  @ 256000
//   features [262656,128]@ 512000   (q | k | queue)
//   labels   [262656]    @ 34131968 (lab, lab, queue_pseudo)
//   score    [256,1000]  @ 34394624
//   protos   [1000,128]  @ 34650624
static const size_t OFF_OUT   = 0;
static const size_t OFF_OUT2  = 256000;
static const size_t OFF_FEAT  = 512000;
static const size_t OFF_LAB   = 34131968;
static const size_t OFF_SCORE = 34394624;
static const size_t OFF_PROT  = 34650624;

// block partition (order matters: argmax first -> wave-1 resident; copy next
// so the DRAM long-pole starts immediately; EMA last so its spin is ~free)
#define ARGMAX_BLOCKS  32
#define QCPY_BLOCKS    2048
#define SCORE_BLOCKS   (NB / RPB)     /* 64  */
#define EMA_BLOCKS     (NC / 2)       /* 500 */
#define SMALLCP_BLOCKS 205
#define B_ARG0   0
#define B_QCPY0  (B_ARG0 + ARGMAX_BLOCKS)
#define B_SCORE0 (B_QCPY0 + QCPY_BLOCKS)
#define B_EMA0   (B_SCORE0 + SCORE_BLOCKS)
#define B_SMCP0  (B_EMA0 + EMA_BLOCKS)
#define TOTAL_BLOCKS (B_SMCP0 + SMALLCP_BLOCKS)

// float4 segment sizes
#define SEG_QUEUE  ((size_t)NQ * ND / 4)   /* 8388608 f4 = 134 MB */
#define SEG_OUT    ((size_t)NB * NC / 4)   /* 64000   */
#define SEG_QK     ((size_t)NB * ND / 4)   /* 8192    */
#define SEG_QP     ((size_t)NQ / 4)        /* 65536   */
#define SMALL_F4   (2*SEG_OUT + 2*SEG_QK + SEG_QP)  /* 209920 */

__device__ int g_labels[NB];
__device__ int g_flag = 0;   // argmax blocks arrive here (-> 32)
__device__ int g_done = 0;   // EMA blocks arrive; last one resets both

// ---------------------------------------------------------------------------
__global__ void __launch_bounds__(256, 6) mega_kernel(
        const float* __restrict__ q,
        const float* __restrict__ k,
        const float* __restrict__ out1,
        const float* __restrict__ out2,
        const float* __restrict__ partial_Y,
        const float* __restrict__ protos,
        const float* __restrict__ queue,
        const float* __restrict__ queue_pseudo,
        float* __restrict__ o) {
    int bid = blockIdx.x;
    int tid = threadIdx.x;

    if (bid < B_QCPY0) {
        // ================= argmax: pseudo-labels (32 blocks) ===============
        // argmax_c( output[b,c]*partial_Y[b,c] ), first-occurrence tie-break.
        int wd   = tid >> 5;
        int lane = tid & 31;
        int b = bid * 8 + wd;
        const float* orow = out1      + (size_t)b * NC;
        const float* mrow = partial_Y + (size_t)b * NC;
        float best = -INFINITY;
        int   bidx = NC;
        for (int c = lane; c < NC; c += 32) {
            float v = orow[c] * mrow[c];
            if (v > best) { best = v; bidx = c; }
        }
#pragma unroll
        for (int off = 16; off > 0; off >>= 1) {
            float ov = __shfl_xor_sync(0xffffffffu, best, off);
            int   oi = __shfl_xor_sync(0xffffffffu, bidx, off);
            if (ov > best || (ov == best && oi < bidx)) { best = ov; bidx = oi; }
        }
        if (lane == 0) {
            g_labels[b] = bidx;
            o[OFF_LAB + b]      = (float)bidx;
            o[OFF_LAB + NB + b] = (float)bidx;
        }
        __syncthreads();
        if (tid == 0) {
            __threadfence();
            atomicAdd(&g_flag, 1);   // release: labels visible
        }
    } else if (bid < B_SCORE0) {
        // ================= queue copy (2048 blocks, branch-free) ===========
        const float4* src = (const float4*)queue;
        float4* dst = (float4*)(o + OFF_FEAT + 2 * (size_t)NB * ND);
        const size_t tile = (size_t)QCPY_BLOCKS * 256 * 4;
        size_t base = (size_t)(bid - B_QCPY0) * (256 * 4) + tid;
#pragma unroll 1
        for (size_t s = base; s < SEG_QUEUE; s += tile) {
            float4 v0 = __ldcs(src + s + 0 * 256);
            float4 v1 = __ldcs(src + s + 1 * 256);
            float4 v2 = __ldcs(src + s + 2 * 256);
            float4 v3 = __ldcs(src + s + 3 * 256);
            __stcs(dst + s + 0 * 256, v0);
            __stcs(dst + s + 1 * 256, v1);
            __stcs(dst + s + 2 * 256, v2);
            __stcs(dst + s + 3 * 256, v3);
        }
    } else if (bid < B_EMA0) {
        // ================= score_prot = softmax(q @ protos^T) ==============
        float* score = o + OFF_SCORE;
        __shared__ float qs[RPB][ND];
        __shared__ float wred[8][RPB];
        int b0 = (bid - B_SCORE0) * RPB;
        for (int i = tid; i < RPB * ND; i += 256)
            qs[i >> 7][i & 127] = q[(size_t)b0 * ND + i];
        __syncthreads();

        float acc[4][RPB];
#pragma unroll
        for (int it = 0; it < 4; it++)
#pragma unroll
            for (int r = 0; r < RPB; r++) acc[it][r] = -INFINITY;

#pragma unroll
        for (int it = 0; it < 4; it++) {
            int c = tid + it * 256;
            if (c < NC) {
                float a[RPB];
#pragma unroll
                for (int r = 0; r < RPB; r++) a[r] = 0.f;
                const float4* prow = (const float4*)(protos + (size_t)c * ND);
#pragma unroll 4
                for (int d4 = 0; d4 < ND / 4; d4++) {
                    float4 p = prow[d4];
#pragma unroll
                    for (int r = 0; r < RPB; r++) {
                        a[r] += p.x * qs[r][d4*4+0] + p.y * qs[r][d4*4+1]
                              + p.z * qs[r][d4*4+2] + p.w * qs[r][d4*4+3];
                    }
                }
#pragma unroll
                for (int r = 0; r < RPB; r++) acc[it][r] = a[r];
            }
        }

        int lane = tid & 31, wd = tid >> 5;
        float rowmax[RPB];
        {
            float mx[RPB];
#pragma unroll
            for (int r = 0; r < RPB; r++) {
                float v = fmaxf(fmaxf(acc[0][r], acc[1][r]),
                                fmaxf(acc[2][r], acc[3][r]));
#pragma unroll
                for (int off = 16; off > 0; off >>= 1)
                    v = fmaxf(v, __shfl_xor_sync(0xffffffffu, v, off));
                mx[r] = v;
            }
            if (lane == 0)
#pragma unroll
                for (int r = 0; r < RPB; r++) wred[wd][r] = mx[r];
            __syncthreads();
#pragma unroll
            for (int r = 0; r < RPB; r++) {
                float v = wred[0][r];
#pragma unroll
                for (int w = 1; w < 8; w++) v = fmaxf(v, wred[w][r]);
                rowmax[r] = v;
            }
            __syncthreads();
        }
        float sm[RPB];
#pragma unroll
        for (int r = 0; r < RPB; r++) sm[r] = 0.f;
#pragma unroll
        for (int it = 0; it < 4; it++) {
            int c = tid + it * 256;
#pragma unroll
            for (int r = 0; r < RPB; r++) {
                float e = (c < NC) ? expf(acc[it][r] - rowmax[r]) : 0.f;
                acc[it][r] = e;
                sm[r] += e;
            }
        }
        float rowsum[RPB];
        {
#pragma unroll
            for (int r = 0; r < RPB; r++) {
                float s = sm[r];
#pragma unroll
                for (int off = 16; off > 0; off >>= 1)
                    s += __shfl_xor_sync(0xffffffffu, s, off);
                sm[r] = s;
            }
            if (lane == 0)
#pragma unroll
                for (int r = 0; r < RPB; r++) wred[wd][r] = sm[r];
            __syncthreads();
#pragma unroll
            for (int r = 0; r < RPB; r++) {
                float s = 0.f;
#pragma unroll
                for (int w = 0; w < 8; w++) s += wred[w][r];
                rowsum[r] = s;
            }
        }
#pragma unroll
        for (int it = 0; it < 4; it++) {
            int c = tid + it * 256;
            if (c < NC) {
#pragma unroll
                for (int r = 0; r < RPB; r++)
                    score[(size_t)(b0 + r) * NC + c] = acc[it][r] / rowsum[r];
            }
        }
    } else if (bid < B_SMCP0) {
        // ================= EMA scatter + L2 normalize (500 blocks) =========
        int part = bid - B_EMA0;
        int c = part * 2 + (tid >> 7);
        int d = tid & 127;
        __shared__ int   lab[NB];
        __shared__ float s8[8];

        if (tid == 0) {  // wait for argmax release
            volatile int* f = &g_flag;
            while (*f != ARGMAX_BLOCKS) { __nanosleep(60); }
        }
        __syncthreads();
        __threadfence();  // acquire: labels now visible

        for (int i = tid; i < NB; i += 256) lab[i] = g_labels[i];
        __syncthreads();

        float val = protos[(size_t)c * ND + d];
        for (int b = 0; b < NB; b++) {
            if (lab[b] == c)
                val = val * 0.99f + 0.01f * q[(size_t)b * ND + d];
        }
        float ss = val * val;
#pragma unroll
        for (int off = 16; off > 0; off >>= 1)
            ss += __shfl_xor_sync(0xffffffffu, ss, off);
        int lane = tid & 31, wd = tid >> 5;
        if (lane == 0) s8[wd] = ss;
        __syncthreads();
        int h = tid >> 7;
        float tot = s8[h*4+0] + s8[h*4+1] + s8[h*4+2] + s8[h*4+3];
        float denom = fmaxf(sqrtf(tot), 1e-12f);
        o[OFF_PROT + (size_t)c * ND + d] = val / denom;

        // last EMA block resets flags for the next graph replay
        __syncthreads();
        if (tid == 0) {
            int prev = atomicAdd(&g_done, 1);
            if (prev == EMA_BLOCKS - 1) {
                g_done = 0;
                __threadfence();
                g_flag = 0;
            }
        }
    } else {
        // ================= small concat copies (3.3 MB, 205 blocks) ========
        size_t idx = (size_t)(bid - B_SMCP0) * 256 + tid;
        const size_t stride = (size_t)SMALLCP_BLOCKS * 256;

        const float4* o14 = (const float4*)out1;
        const float4* o24 = (const float4*)out2;
        const float4* q4  = (const float4*)q;
        const float4* k4  = (const float4*)k;
        const float4* qp4 = (const float4*)queue_pseudo;
        float4* d_o1 = (float4*)(o + OFF_OUT);
        float4* d_o2 = (float4*)(o + OFF_OUT2);
        float4* d_q  = (float4*)(o + OFF_FEAT);
        float4* d_k  = (float4*)(o + OFF_FEAT + (size_t)NB * ND);
        float4* d_qp = (float4*)(o + OFF_LAB + 2 * NB);

        for (; idx < SMALL_F4; idx += stride) {
            size_t i = idx;
            if (i < SEG_OUT) { d_o1[i] = o14[i]; continue; }
            i -= SEG_OUT;
            if (i < SEG_OUT) { d_o2[i] = o24[i]; continue; }
            i -= SEG_OUT;
            if (i < SEG_QK)  { d_q[i]  = q4[i];  continue; }
            i -= SEG_QK;
            if (i < SEG_QK)  { d_k[i]  = k4[i];  continue; }
            i -= SEG_QK;
            d_qp[i] = qp4[i];
        }
    }
}

// ---------------------------------------------------------------------------
extern "C" void kernel_launch(void* const* d_in, const int* in_sizes, int n_in,
                              void* d_out, int out_size) {
    const float* q            = (const float*)d_in[0];
    const float* k            = (const float*)d_in[1];
    const float* out1         = (const float*)d_in[2];
    const float* out2         = (const float*)d_in[3];
    const float* partial_Y    = (const float*)d_in[4];
    const float* protos       = (const float*)d_in[5];
    const float* queue        = (const float*)d_in[6];
    const float* queue_pseudo = (const float*)d_in[7];
    float* o = (float*)d_out;

    mega_kernel<<<TOTAL_BLOCKS, 256>>>(q, k, out1, out2, partial_Y, protos,
                                       queue, queue_pseudo, o);
}

// round 7
// speedup vs baseline: 1.8800x; 1.8800x over previous
#include <cuda_runtime.h>
#include <math.h>

#define NB 256
#define NC 1000
#define ND 128
#define NQ 262144
#define RPB 4

// d_out flat layout (in-order tuple concat):
//   output   [256,1000]  @ 0
//   output2  [256,1000]  @ 256000
//   features [262656,128]@ 512000   (q | k | queue)
//   labels   [262656]    @ 34131968 (lab, lab, queue_pseudo)
//   score    [256,1000]  @ 34394624
//   protos   [1000,128]  @ 34650624
static const size_t OFF_OUT   = 0;
static const size_t OFF_OUT2  = 256000;
static const size_t OFF_FEAT  = 512000;
static const size_t OFF_LAB   = 34131968;
static const size_t OFF_SCORE = 34394624;
static const size_t OFF_PROT  = 34650624;

// block partition — ORDER IS THE SCHEDULE:
// small compute work first (wave-1 resident, finishes early), giant copy LAST
// so it overlaps everything and the final waves are pure, even copy work.
#define ARGMAX_BLOCKS  32
#define SCORE_BLOCKS   (NB / RPB)     /* 64  */
#define EMA_BLOCKS     (NC / 2)       /* 500 */
#define SMALLCP_BLOCKS 205
#define QCPY_BLOCKS    2048
#define B_ARG0   0
#define B_SCORE0 (B_ARG0 + ARGMAX_BLOCKS)
#define B_EMA0   (B_SCORE0 + SCORE_BLOCKS)
#define B_SMCP0  (B_EMA0 + EMA_BLOCKS)
#define B_QCPY0  (B_SMCP0 + SMALLCP_BLOCKS)
#define TOTAL_BLOCKS (B_QCPY0 + QCPY_BLOCKS)

// float4 segment sizes
#define SEG_QUEUE  ((size_t)NQ * ND / 4)   /* 8388608 f4 = 134 MB */
#define SEG_OUT    ((size_t)NB * NC / 4)   /* 64000   */
#define SEG_QK     ((size_t)NB * ND / 4)   /* 8192    */
#define SEG_QP     ((size_t)NQ / 4)        /* 65536   */
#define SMALL_F4   (2*SEG_OUT + 2*SEG_QK + SEG_QP)  /* 209920 */

__device__ int g_labels[NB];
__device__ int g_flag = 0;   // argmax blocks arrive (-> 32)
__device__ int g_done = 0;   // EMA blocks arrive; last one resets both

// ---------------------------------------------------------------------------
__global__ void __launch_bounds__(256) mega_kernel(
        const float* __restrict__ q,
        const float* __restrict__ k,
        const float* __restrict__ out1,
        const float* __restrict__ out2,
        const float* __restrict__ partial_Y,
        const float* __restrict__ protos,
        const float* __restrict__ queue,
        const float* __restrict__ queue_pseudo,
        float* __restrict__ o) {
    int bid = blockIdx.x;
    int tid = threadIdx.x;

    if (bid < B_SCORE0) {
        // ================= argmax: pseudo-labels (32 blocks) ===============
        // argmax_c( output[b,c]*partial_Y[b,c] ), first-occurrence tie-break.
        int wd   = tid >> 5;
        int lane = tid & 31;
        int b = bid * 8 + wd;
        const float* orow = out1      + (size_t)b * NC;
        const float* mrow = partial_Y + (size_t)b * NC;
        float best = -INFINITY;
        int   bidx = NC;
        for (int c = lane; c < NC; c += 32) {
            float v = orow[c] * mrow[c];
            if (v > best) { best = v; bidx = c; }
        }
#pragma unroll
        for (int off = 16; off > 0; off >>= 1) {
            float ov = __shfl_xor_sync(0xffffffffu, best, off);
            int   oi = __shfl_xor_sync(0xffffffffu, bidx, off);
            if (ov > best || (ov == best && oi < bidx)) { best = ov; bidx = oi; }
        }
        if (lane == 0) {
            g_labels[b] = bidx;
            o[OFF_LAB + b]      = (float)bidx;
            o[OFF_LAB + NB + b] = (float)bidx;
        }
        __syncthreads();
        if (tid == 0) {
            __threadfence();
            atomicAdd(&g_flag, 1);   // release: labels visible
        }
    } else if (bid < B_EMA0) {
        // ================= score_prot = softmax(q @ protos^T) ==============
        float* score = o + OFF_SCORE;
        __shared__ float qs[RPB][ND];
        __shared__ float wred[8][RPB];
        int b0 = (bid - B_SCORE0) * RPB;
        for (int i = tid; i < RPB * ND; i += 256)
            qs[i >> 7][i & 127] = q[(size_t)b0 * ND + i];
        __syncthreads();

        float acc[4][RPB];
#pragma unroll
        for (int it = 0; it < 4; it++)
#pragma unroll
            for (int r = 0; r < RPB; r++) acc[it][r] = -INFINITY;

#pragma unroll
        for (int it = 0; it < 4; it++) {
            int c = tid + it * 256;
            if (c < NC) {
                float a[RPB];
#pragma unroll
                for (int r = 0; r < RPB; r++) a[r] = 0.f;
                const float4* prow = (const float4*)(protos + (size_t)c * ND);
#pragma unroll 4
                for (int d4 = 0; d4 < ND / 4; d4++) {
                    float4 p = prow[d4];
#pragma unroll
                    for (int r = 0; r < RPB; r++) {
                        a[r] += p.x * qs[r][d4*4+0] + p.y * qs[r][d4*4+1]
                              + p.z * qs[r][d4*4+2] + p.w * qs[r][d4*4+3];
                    }
                }
#pragma unroll
                for (int r = 0; r < RPB; r++) acc[it][r] = a[r];
            }
        }

        int lane = tid & 31, wd = tid >> 5;
        float rowmax[RPB];
        {
            float mx[RPB];
#pragma unroll
            for (int r = 0; r < RPB; r++) {
                float v = fmaxf(fmaxf(acc[0][r], acc[1][r]),
                                fmaxf(acc[2][r], acc[3][r]));
#pragma unroll
                for (int off = 16; off > 0; off >>= 1)
                    v = fmaxf(v, __shfl_xor_sync(0xffffffffu, v, off));
                mx[r] = v;
            }
            if (lane == 0)
#pragma unroll
                for (int r = 0; r < RPB; r++) wred[wd][r] = mx[r];
            __syncthreads();
#pragma unroll
            for (int r = 0; r < RPB; r++) {
                float v = wred[0][r];
#pragma unroll
                for (int w = 1; w < 8; w++) v = fmaxf(v, wred[w][r]);
                rowmax[r] = v;
            }
            __syncthreads();
        }
        float sm[RPB];
#pragma unroll
        for (int r = 0; r < RPB; r++) sm[r] = 0.f;
#pragma unroll
        for (int it = 0; it < 4; it++) {
            int c = tid + it * 256;
#pragma unroll
            for (int r = 0; r < RPB; r++) {
                float e = (c < NC) ? expf(acc[it][r] - rowmax[r]) : 0.f;
                acc[it][r] = e;
                sm[r] += e;
            }
        }
        float rowsum[RPB];
        {
#pragma unroll
            for (int r = 0; r < RPB; r++) {
                float s = sm[r];
#pragma unroll
                for (int off = 16; off > 0; off >>= 1)
                    s += __shfl_xor_sync(0xffffffffu, s, off);
                sm[r] = s;
            }
            if (lane == 0)
#pragma unroll
                for (int r = 0; r < RPB; r++) wred[wd][r] = sm[r];
            __syncthreads();
#pragma unroll
            for (int r = 0; r < RPB; r++) {
                float s = 0.f;
#pragma unroll
                for (int w = 0; w < 8; w++) s += wred[w][r];
                rowsum[r] = s;
            }
        }
#pragma unroll
        for (int it = 0; it < 4; it++) {
            int c = tid + it * 256;
            if (c < NC) {
#pragma unroll
                for (int r = 0; r < RPB; r++)
                    score[(size_t)(b0 + r) * NC + c] = acc[it][r] / rowsum[r];
            }
        }
    } else if (bid < B_SMCP0) {
        // ================= EMA scatter + L2 normalize (500 blocks) =========
        int part = bid - B_EMA0;
        int c = part * 2 + (tid >> 7);
        int d = tid & 127;
        __shared__ int   lab[NB];
        __shared__ float s8[8];

        if (tid == 0) {  // wait for argmax release (argmax is wave-1 resident)
            volatile int* f = &g_flag;
            while (*f != ARGMAX_BLOCKS) { __nanosleep(60); }
        }
        __syncthreads();
        __threadfence();  // acquire

        for (int i = tid; i < NB; i += 256) lab[i] = g_labels[i];
        __syncthreads();

        float val = protos[(size_t)c * ND + d];
        for (int b = 0; b < NB; b++) {
            if (lab[b] == c)
                val = val * 0.99f + 0.01f * q[(size_t)b * ND + d];
        }
        float ss = val * val;
#pragma unroll
        for (int off = 16; off > 0; off >>= 1)
            ss += __shfl_xor_sync(0xffffffffu, ss, off);
        int lane = tid & 31, wd = tid >> 5;
        if (lane == 0) s8[wd] = ss;
        __syncthreads();
        int h = tid >> 7;
        float tot = s8[h*4+0] + s8[h*4+1] + s8[h*4+2] + s8[h*4+3];
        float denom = fmaxf(sqrtf(tot), 1e-12f);
        o[OFF_PROT + (size_t)c * ND + d] = val / denom;

        // last EMA block resets flags for the next graph replay
        __syncthreads();
        if (tid == 0) {
            int prev = atomicAdd(&g_done, 1);
            if (prev == EMA_BLOCKS - 1) {
                g_done = 0;
                __threadfence();
                g_flag = 0;
            }
        }
    } else if (bid < B_QCPY0) {
        // ================= small concat copies (3.3 MB, 205 blocks) ========
        size_t idx = (size_t)(bid - B_SMCP0) * 256 + tid;
        const size_t stride = (size_t)SMALLCP_BLOCKS * 256;

        const float4* o14 = (const float4*)out1;
        const float4* o24 = (const float4*)out2;
        const float4* q4  = (const float4*)q;
        const float4* k4  = (const float4*)k;
        const float4* qp4 = (const float4*)queue_pseudo;
        float4* d_o1 = (float4*)(o + OFF_OUT);
        float4* d_o2 = (float4*)(o + OFF_OUT2);
        float4* d_q  = (float4*)(o + OFF_FEAT);
        float4* d_k  = (float4*)(o + OFF_FEAT + (size_t)NB * ND);
        float4* d_qp = (float4*)(o + OFF_LAB + 2 * NB);

        for (; idx < SMALL_F4; idx += stride) {
            size_t i = idx;
            if (i < SEG_OUT) { d_o1[i] = o14[i]; continue; }
            i -= SEG_OUT;
            if (i < SEG_OUT) { d_o2[i] = o24[i]; continue; }
            i -= SEG_OUT;
            if (i < SEG_QK)  { d_q[i]  = q4[i];  continue; }
            i -= SEG_QK;
            if (i < SEG_QK)  { d_k[i]  = k4[i];  continue; }
            i -= SEG_QK;
            d_qp[i] = qp4[i];
        }
    } else {
        // ================= queue copy (2048 blocks, LAST, branch-free) =====
        const float4* src = (const float4*)queue;
        float4* dst = (float4*)(o + OFF_FEAT + 2 * (size_t)NB * ND);
        const size_t tile = (size_t)QCPY_BLOCKS * 256 * 4;
        size_t base = (size_t)(bid - B_QCPY0) * (256 * 4) + tid;
#pragma unroll 1
        for (size_t s = base; s < SEG_QUEUE; s += tile) {
            float4 v0 = __ldcs(src + s + 0 * 256);
            float4 v1 = __ldcs(src + s + 1 * 256);
            float4 v2 = __ldcs(src + s + 2 * 256);
            float4 v3 = __ldcs(src + s + 3 * 256);
            __stcs(dst + s + 0 * 256, v0);
            __stcs(dst + s + 1 * 256, v1);
            __stcs(dst + s + 2 * 256, v2);
            __stcs(dst + s + 3 * 256, v3);
        }
    }
}

// ---------------------------------------------------------------------------
extern "C" void kernel_launch(void* const* d_in, const int* in_sizes, int n_in,
                              void* d_out, int out_size) {
    const float* q            = (const float*)d_in[0];
    const float* k            = (const float*)d_in[1];
    const float* out1         = (const float*)d_in[2];
    const float* out2         = (const float*)d_in[3];
    const float* partial_Y    = (const float*)d_in[4];
    const float* protos       = (const float*)d_in[5];
    const float* queue        = (const float*)d_in[6];
    const float* queue_pseudo = (const float*)d_in[7];
    float* o = (float*)d_out;

    mega_kernel<<<TOTAL_BLOCKS, 256>>>(q, k, out1, out2, partial_Y, protos,
                                       queue, queue_pseudo, o);
}

// round 9
// speedup vs baseline: 1.8831x; 1.0017x over previous
#include <cuda_runtime.h>
#include <math.h>

#define NB 256
#define NC 1000
#define ND 128
#define NQ 262144
#define RPB 4

// d_out flat layout (in-order tuple concat):
//   output   [256,1000]  @ 0
//   output2  [256,1000]  @ 256000
//   features [262656,128]@ 512000   (q | k | queue)
//   labels   [262656]    @ 34131968 (lab, lab, queue_pseudo)
//   score    [256,1000]  @ 34394624
//   protos   [1000,128]  @ 34650624
static const size_t OFF_OUT   = 0;
static const size_t OFF_OUT2  = 256000;
static const size_t OFF_FEAT  = 512000;
static const size_t OFF_LAB   = 34131968;
static const size_t OFF_SCORE = 34394624;
static const size_t OFF_PROT  = 34650624;

// block partition — ORDER IS THE SCHEDULE:
// small compute work first (wave-1 resident, finishes early), giant copy LAST.
#define ARGMAX_BLOCKS  32
#define SCORE_BLOCKS   (NB / RPB)     /* 64  */
#define EMA_BLOCKS     (NC / 2)       /* 500 */
#define SMALLCP_BLOCKS 205
#define QCPY_BLOCKS    4096           /* 4096 * 256 * 8 f4 == SEG_QUEUE exactly */
#define B_ARG0   0
#define B_SCORE0 (B_ARG0 + ARGMAX_BLOCKS)
#define B_EMA0   (B_SCORE0 + SCORE_BLOCKS)
#define B_SMCP0  (B_EMA0 + EMA_BLOCKS)
#define B_QCPY0  (B_SMCP0 + SMALLCP_BLOCKS)
#define TOTAL_BLOCKS (B_QCPY0 + QCPY_BLOCKS)

// float4 segment sizes
#define SEG_QUEUE  ((size_t)NQ * ND / 4)   /* 8388608 f4 = 134 MB */
#define SEG_OUT    ((size_t)NB * NC / 4)   /* 64000   */
#define SEG_QK     ((size_t)NB * ND / 4)   /* 8192    */
#define SEG_QP     ((size_t)NQ / 4)        /* 65536   */
#define SMALL_F4   (2*SEG_OUT + 2*SEG_QK + SEG_QP)  /* 209920 */

__device__ int g_labels[NB];
__device__ int g_flag = 0;   // argmax blocks arrive (-> 32)
__device__ int g_done = 0;   // EMA blocks arrive; last one resets both

// ---------------------------------------------------------------------------
__global__ void __launch_bounds__(256, 6) mega_kernel(
        const float* __restrict__ q,
        const float* __restrict__ k,
        const float* __restrict__ out1,
        const float* __restrict__ out2,
        const float* __restrict__ partial_Y,
        const float* __restrict__ protos,
        const float* __restrict__ queue,
        const float* __restrict__ queue_pseudo,
        float* __restrict__ o) {
    int bid = blockIdx.x;
    int tid = threadIdx.x;

    if (bid >= B_QCPY0) {
        // ================= queue copy (4096 blocks, LAST in grid) ==========
        // Exactly one unroll-8 batch per thread: 8 independent loads
        // front-batched (MLP=8), then 8 streaming stores. Branch-free.
        const float4* src = (const float4*)queue;
        float4* dst = (float4*)(o + OFF_FEAT + 2 * (size_t)NB * ND);
        size_t s = (size_t)(bid - B_QCPY0) * (256 * 8) + tid;
        float4 v0 = __ldcs(src + s + 0 * 256);
        float4 v1 = __ldcs(src + s + 1 * 256);
        float4 v2 = __ldcs(src + s + 2 * 256);
        float4 v3 = __ldcs(src + s + 3 * 256);
        float4 v4 = __ldcs(src + s + 4 * 256);
        float4 v5 = __ldcs(src + s + 5 * 256);
        float4 v6 = __ldcs(src + s + 6 * 256);
        float4 v7 = __ldcs(src + s + 7 * 256);
        __stcs(dst + s + 0 * 256, v0);
        __stcs(dst + s + 1 * 256, v1);
        __stcs(dst + s + 2 * 256, v2);
        __stcs(dst + s + 3 * 256, v3);
        __stcs(dst + s + 4 * 256, v4);
        __stcs(dst + s + 5 * 256, v5);
        __stcs(dst + s + 6 * 256, v6);
        __stcs(dst + s + 7 * 256, v7);
        return;
    }

    if (bid < B_SCORE0) {
        // ================= argmax: pseudo-labels (32 blocks) ===============
        // argmax_c( output[b,c]*partial_Y[b,c] ), first-occurrence tie-break.
        int wd   = tid >> 5;
        int lane = tid & 31;
        int b = bid * 8 + wd;
        const float* orow = out1      + (size_t)b * NC;
        const float* mrow = partial_Y + (size_t)b * NC;
        float best = -INFINITY;
        int   bidx = NC;
        for (int c = lane; c < NC; c += 32) {
            float v = orow[c] * mrow[c];
            if (v > best) { best = v; bidx = c; }
        }
#pragma unroll
        for (int off = 16; off > 0; off >>= 1) {
            float ov = __shfl_xor_sync(0xffffffffu, best, off);
            int   oi = __shfl_xor_sync(0xffffffffu, bidx, off);
            if (ov > best || (ov == best && oi < bidx)) { best = ov; bidx = oi; }
        }
        if (lane == 0) {
            g_labels[b] = bidx;
            o[OFF_LAB + b]      = (float)bidx;
            o[OFF_LAB + NB + b] = (float)bidx;
        }
        __syncthreads();
        if (tid == 0) {
            __threadfence();
            atomicAdd(&g_flag, 1);   // release: labels visible
        }
    } else if (bid < B_EMA0) {
        // ================= score_prot = softmax(q @ protos^T) ==============
        float* score = o + OFF_SCORE;
        __shared__ float qs[RPB][ND];
        __shared__ float wred[8][RPB];
        int b0 = (bid - B_SCORE0) * RPB;
        for (int i = tid; i < RPB * ND; i += 256)
            qs[i >> 7][i & 127] = q[(size_t)b0 * ND + i];
        __syncthreads();

        float acc[4][RPB];
#pragma unroll
        for (int it = 0; it < 4; it++)
#pragma unroll
            for (int r = 0; r < RPB; r++) acc[it][r] = -INFINITY;

#pragma unroll
        for (int it = 0; it < 4; it++) {
            int c = tid + it * 256;
            if (c < NC) {
                float a[RPB];
#pragma unroll
                for (int r = 0; r < RPB; r++) a[r] = 0.f;
                const float4* prow = (const float4*)(protos + (size_t)c * ND);
#pragma unroll 4
                for (int d4 = 0; d4 < ND / 4; d4++) {
                    float4 p = prow[d4];
#pragma unroll
                    for (int r = 0; r < RPB; r++) {
                        a[r] += p.x * qs[r][d4*4+0] + p.y * qs[r][d4*4+1]
                              + p.z * qs[r][d4*4+2] + p.w * qs[r][d4*4+3];
                    }
                }
#pragma unroll
                for (int r = 0; r < RPB; r++) acc[it][r] = a[r];
            }
        }

        int lane = tid & 31, wd = tid >> 5;
        float rowmax[RPB];
        {
            float mx[RPB];
#pragma unroll
            for (int r = 0; r < RPB; r++) {
                float v = fmaxf(fmaxf(acc[0][r], acc[1][r]),
                                fmaxf(acc[2][r], acc[3][r]));
#pragma unroll
                for (int off = 16; off > 0; off >>= 1)
                    v = fmaxf(v, __shfl_xor_sync(0xffffffffu, v, off));
                mx[r] = v;
            }
            if (lane == 0)
#pragma unroll
                for (int r = 0; r < RPB; r++) wred[wd][r] = mx[r];
            __syncthreads();
#pragma unroll
            for (int r = 0; r < RPB; r++) {
                float v = wred[0][r];
#pragma unroll
                for (int w = 1; w < 8; w++) v = fmaxf(v, wred[w][r]);
                rowmax[r] = v;
            }
            __syncthreads();
        }
        float sm[RPB];
#pragma unroll
        for (int r = 0; r < RPB; r++) sm[r] = 0.f;
#pragma unroll
        for (int it = 0; it < 4; it++) {
            int c = tid + it * 256;
#pragma unroll
            for (int r = 0; r < RPB; r++) {
                float e = (c < NC) ? expf(acc[it][r] - rowmax[r]) : 0.f;
                acc[it][r] = e;
                sm[r] += e;
            }
        }
        float rowsum[RPB];
        {
#pragma unroll
            for (int r = 0; r < RPB; r++) {
                float s = sm[r];
#pragma unroll
                for (int off = 16; off > 0; off >>= 1)
                    s += __shfl_xor_sync(0xffffffffu, s, off);
                sm[r] = s;
            }
            if (lane == 0)
#pragma unroll
                for (int r = 0; r < RPB; r++) wred[wd][r] = sm[r];
            __syncthreads();
#pragma unroll
            for (int r = 0; r < RPB; r++) {
                float s = 0.f;
#pragma unroll
                for (int w = 0; w < 8; w++) s += wred[w][r];
                rowsum[r] = s;
            }
        }
#pragma unroll
        for (int it = 0; it < 4; it++) {
            int c = tid + it * 256;
            if (c < NC) {
#pragma unroll
                for (int r = 0; r < RPB; r++)
                    score[(size_t)(b0 + r) * NC + c] = acc[it][r] / rowsum[r];
            }
        }
    } else if (bid < B_SMCP0) {
        // ================= EMA scatter + L2 normalize (500 blocks) =========
        int part = bid - B_EMA0;
        int c = part * 2 + (tid >> 7);
        int d = tid & 127;
        __shared__ int   lab[NB];
        __shared__ float s8[8];

        if (tid == 0) {  // wait for argmax release (argmax is wave-1 resident)
            volatile int* f = &g_flag;
            while (*f != ARGMAX_BLOCKS) { __nanosleep(60); }
        }
        __syncthreads();
        __threadfence();  // acquire

        for (int i = tid; i < NB; i += 256) lab[i] = g_labels[i];
        __syncthreads();

        float val = protos[(size_t)c * ND + d];
        for (int b = 0; b < NB; b++) {
            if (lab[b] == c)
                val = val * 0.99f + 0.01f * q[(size_t)b * ND + d];
        }
        float ss = val * val;
#pragma unroll
        for (int off = 16; off > 0; off >>= 1)
            ss += __shfl_xor_sync(0xffffffffu, ss, off);
        int lane = tid & 31, wd = tid >> 5;
        if (lane == 0) s8[wd] = ss;
        __syncthreads();
        int h = tid >> 7;
        float tot = s8[h*4+0] + s8[h*4+1] + s8[h*4+2] + s8[h*4+3];
        float denom = fmaxf(sqrtf(tot), 1e-12f);
        o[OFF_PROT + (size_t)c * ND + d] = val / denom;

        // last EMA block resets flags for the next graph replay
        __syncthreads();
        if (tid == 0) {
            int prev = atomicAdd(&g_done, 1);
            if (prev == EMA_BLOCKS - 1) {
                g_done = 0;
                __threadfence();
                g_flag = 0;
            }
        }
    } else {
        // ================= small concat copies (3.3 MB, 205 blocks) ========
        size_t idx = (size_t)(bid - B_SMCP0) * 256 + tid;
        const size_t stride = (size_t)SMALLCP_BLOCKS * 256;

        const float4* o14 = (const float4*)out1;
        const float4* o24 = (const float4*)out2;
        const float4* q4  = (const float4*)q;
        const float4* k4  = (const float4*)k;
        const float4* qp4 = (const float4*)queue_pseudo;
        float4* d_o1 = (float4*)(o + OFF_OUT);
        float4* d_o2 = (float4*)(o + OFF_OUT2);
        float4* d_q  = (float4*)(o + OFF_FEAT);
        float4* d_k  = (float4*)(o + OFF_FEAT + (size_t)NB * ND);
        float4* d_qp = (float4*)(o + OFF_LAB + 2 * NB);

        for (; idx < SMALL_F4; idx += stride) {
            size_t i = idx;
            if (i < SEG_OUT) { d_o1[i] = o14[i]; continue; }
            i -= SEG_OUT;
            if (i < SEG_OUT) { d_o2[i] = o24[i]; continue; }
            i -= SEG_OUT;
            if (i < SEG_QK)  { d_q[i]  = q4[i];  continue; }
            i -= SEG_QK;
            if (i < SEG_QK)  { d_k[i]  = k4[i];  continue; }
            i -= SEG_QK;
            d_qp[i] = qp4[i];
        }
    }
}

// ---------------------------------------------------------------------------
extern "C" void kernel_launch(void* const* d_in, const int* in_sizes, int n_in,
                              void* d_out, int out_size) {
    const float* q            = (const float*)d_in[0];
    const float* k            = (const float*)d_in[1];
    const float* out1         = (const float*)d_in[2];
    const float* out2         = (const float*)d_in[3];
    const float* partial_Y    = (const float*)d_in[4];
    const float* protos       = (const float*)d_in[5];
    const float* queue        = (const float*)d_in[6];
    const float* queue_pseudo = (const float*)d_in[7];
    float* o = (float*)d_out;

    mega_kernel<<<TOTAL_BLOCKS, 256>>>(q, k, out1, out2, partial_Y, protos,
                                       queue, queue_pseudo, o);
}